// round 1
// baseline (speedup 1.0000x reference)
#include <cuda_runtime.h>

#define NNODES 100000
#define NEDGES 1600000
#define DIN 256
#define DH 128
#define DOUT 64
#define BN_EPS 1e-5f

// ---------------- static device scratch (no allocations allowed) ----------------
__device__ float g_dinv[NNODES];
__device__ int   g_deg[NNODES];
__device__ int   g_cursor[NNODES];
__device__ int   g_rowptr[NNODES + 1];
__device__ int   g_col[NEDGES];
__device__ float g_wgt[NEDGES];
__device__ float g_H [NNODES * DH];   // GEMM output (XW)
__device__ float g_A [NNODES * DH];   // aggregated conv output
__device__ float g_Hn[NNODES * DH];   // BN+ReLU output (input to next GEMM)
__device__ float g_stats[2 * DH];     // column sums / sumsq
__device__ float g_scale[DH];
__device__ float g_shift[DH];

// ---------------- setup kernels ----------------
__global__ void k_zero_node_ints() {
    int i = blockIdx.x * blockDim.x + threadIdx.x;
    if (i < NNODES) { g_deg[i] = 0; g_cursor[i] = 0; }
}

__global__ void k_count_deg(const int* __restrict__ ei, int E) {
    int e = blockIdx.x * blockDim.x + threadIdx.x;
    if (e < E) atomicAdd(&g_deg[ei[E + e]], 1);   // dst = ei[1][e]
}

__global__ void k_dinv() {
    int i = blockIdx.x * blockDim.x + threadIdx.x;
    if (i < NNODES) g_dinv[i] = rsqrtf((float)(g_deg[i] + 1));  // +1 self loop
}

// single-block exclusive scan of g_deg -> g_rowptr
__global__ void k_scan(int n, int total) {
    __shared__ int ssum[1024];
    int t = threadIdx.x;
    int chunk = (n + 1023) / 1024;
    int lo = t * chunk;
    int hi = min(lo + chunk, n);
    int s = 0;
    for (int i = lo; i < hi; i++) s += g_deg[i];
    ssum[t] = s;
    __syncthreads();
    for (int off = 1; off < 1024; off <<= 1) {
        int v = (t >= off) ? ssum[t - off] : 0;
        __syncthreads();
        ssum[t] += v;
        __syncthreads();
    }
    int run = (t == 0) ? 0 : ssum[t - 1];
    for (int i = lo; i < hi; i++) { g_rowptr[i] = run; run += g_deg[i]; }
    if (t == 0) g_rowptr[n] = total;
}

__global__ void k_scatter(const int* __restrict__ ei, int E) {
    int e = blockIdx.x * blockDim.x + threadIdx.x;
    if (e >= E) return;
    int s = ei[e];
    int d = ei[E + e];
    int pos = g_rowptr[d] + atomicAdd(&g_cursor[d], 1);
    g_col[pos] = s;
    g_wgt[pos] = g_dinv[s] * g_dinv[d];
}

// ---------------- fp32 tiled GEMM: C(g_H) = A @ B,  BM=128, TM=8 ----------------
// A: [M,K] row-major (external if EXT_A, else g_Hn), B: [K,BN] row-major, C stride BN
template <int BN, int TN, int BK, bool EXT_A>
__global__ void __launch_bounds__(256)
k_gemm(const float* __restrict__ Aext, const float* __restrict__ B, int M, int K) {
    constexpr int BM = 128, TM = 8;
    constexpr int TCOLS = BN / TN;           // 16
    constexpr int THREADS = 16 * TCOLS;      // 256
    static_assert(THREADS == 256, "thread cfg");
    __shared__ float As[BK][BM];
    __shared__ float Bs[BK][BN];

    const float* A = EXT_A ? Aext : g_Hn;
    float* C = g_H;

    int tid = threadIdx.x;
    int tr = tid / TCOLS;
    int tc = tid % TCOLS;
    int row0 = blockIdx.x * BM;

    float acc[TM][TN];
#pragma unroll
    for (int i = 0; i < TM; i++)
#pragma unroll
        for (int j = 0; j < TN; j++) acc[i][j] = 0.f;

    constexpr int K4 = BK / 4;
    int aRow = tid / K4;
    int aK4  = tid % K4;
    constexpr int AROWS = THREADS / K4;      // rows per pass

    constexpr int N4 = BN / 4;
    int bK  = tid / N4;
    int bN4 = tid % N4;
    constexpr int BROWS = THREADS / N4;

    for (int kt = 0; kt < K; kt += BK) {
#pragma unroll
        for (int p = 0; p < BM / AROWS; p++) {
            int m = aRow + p * AROWS;
            int gr = row0 + m;
            float4 v = make_float4(0.f, 0.f, 0.f, 0.f);
            if (gr < M) v = *(const float4*)(A + (size_t)gr * K + kt + aK4 * 4);
            As[aK4 * 4 + 0][m] = v.x;
            As[aK4 * 4 + 1][m] = v.y;
            As[aK4 * 4 + 2][m] = v.z;
            As[aK4 * 4 + 3][m] = v.w;
        }
#pragma unroll
        for (int p = 0; p < BK / BROWS; p++) {
            int k = bK + p * BROWS;
            float4 v = *(const float4*)(B + (size_t)(kt + k) * BN + bN4 * 4);
            *(float4*)&Bs[k][bN4 * 4] = v;
        }
        __syncthreads();
#pragma unroll
        for (int k = 0; k < BK; k++) {
            float ra[TM], rb[TN];
#pragma unroll
            for (int i = 0; i < TM; i++) ra[i] = As[k][tr * TM + i];
#pragma unroll
            for (int j = 0; j < TN; j++) rb[j] = Bs[k][tc * TN + j];
#pragma unroll
            for (int i = 0; i < TM; i++)
#pragma unroll
                for (int j = 0; j < TN; j++) acc[i][j] += ra[i] * rb[j];
        }
        __syncthreads();
    }
#pragma unroll
    for (int i = 0; i < TM; i++) {
        int gr = row0 + tr * TM + i;
        if (gr >= M) continue;
#pragma unroll
        for (int j4 = 0; j4 < TN / 4; j4++) {
            float4 v = make_float4(acc[i][j4 * 4 + 0], acc[i][j4 * 4 + 1],
                                   acc[i][j4 * 4 + 2], acc[i][j4 * 4 + 3]);
            *(float4*)(C + (size_t)gr * BN + tc * TN + j4 * 4) = v;
        }
    }
}

// ---------------- aggregation: warp per dst node, CSR gather-sum ----------------
// out[i] = bias + dinv[i]^2 * H[i] + sum_e wgt_e * H[col_e]
template <int D, bool EXT_OUT>
__global__ void k_agg(const float* __restrict__ bias, float* __restrict__ out_ext) {
    constexpr int VEC = D / 32;  // 4 (D=128) or 2 (D=64)
    int w = blockIdx.x * (blockDim.x >> 5) + (threadIdx.x >> 5);
    if (w >= NNODES) return;
    int lane = threadIdx.x & 31;
    int base = lane * VEC;
    const float* H = g_H;
    float* out = EXT_OUT ? out_ext : g_A;

    float acc[VEC];
    float di = g_dinv[w];
    float self = di * di;

    if constexpr (VEC == 4) {
        float4 h = *(const float4*)(H + (size_t)w * D + base);
        acc[0] = bias[base + 0] + self * h.x;
        acc[1] = bias[base + 1] + self * h.y;
        acc[2] = bias[base + 2] + self * h.z;
        acc[3] = bias[base + 3] + self * h.w;
    } else {
        float2 h = *(const float2*)(H + (size_t)w * D + base);
        acc[0] = bias[base + 0] + self * h.x;
        acc[1] = bias[base + 1] + self * h.y;
    }

    int jstart = g_rowptr[w];
    int jend   = g_rowptr[w + 1];
    for (int j = jstart; j < jend; j++) {
        int   s  = __ldg(&g_col[j]);
        float wt = __ldg(&g_wgt[j]);
        const float* hp = H + (size_t)s * D + base;
        if constexpr (VEC == 4) {
            float4 h = *(const float4*)hp;
            acc[0] += wt * h.x; acc[1] += wt * h.y;
            acc[2] += wt * h.z; acc[3] += wt * h.w;
        } else {
            float2 h = *(const float2*)hp;
            acc[0] += wt * h.x; acc[1] += wt * h.y;
        }
    }

    if constexpr (VEC == 4) {
        *(float4*)(out + (size_t)w * D + base) = make_float4(acc[0], acc[1], acc[2], acc[3]);
    } else {
        *(float2*)(out + (size_t)w * D + base) = make_float2(acc[0], acc[1]);
    }
}

// ---------------- BatchNorm ----------------
__global__ void k_zero_stats() {
    int t = threadIdx.x;
    if (t < 2 * DH) g_stats[t] = 0.f;
}

__global__ void k_stats() {
    int col = threadIdx.x & (DH - 1);
    int rsub = threadIdx.x >> 7;         // 2 rows per block-iteration
    float s = 0.f, sq = 0.f;
    for (int row = blockIdx.x * 2 + rsub; row < NNODES; row += gridDim.x * 2) {
        float v = g_A[(size_t)row * DH + col];
        s += v; sq += v * v;
    }
    atomicAdd(&g_stats[col], s);
    atomicAdd(&g_stats[DH + col], sq);
}

__global__ void k_bnfinal(const float* __restrict__ g, const float* __restrict__ bt) {
    int t = threadIdx.x;
    if (t >= DH) return;
    float invN = 1.0f / (float)NNODES;
    float mu = g_stats[t] * invN;
    float var = g_stats[DH + t] * invN - mu * mu;
    float r = rsqrtf(var + BN_EPS);
    float a = g[t] * r;
    g_scale[t] = a;
    g_shift[t] = bt[t] - mu * a;
}

__global__ void k_apply_relu() {
    int idx = blockIdx.x * blockDim.x + threadIdx.x;
    constexpr int TOTAL = NNODES * (DH / 4);
    if (idx >= TOTAL) return;
    int c4 = idx & (DH / 4 - 1);
    float4 h = ((const float4*)g_A)[idx];
    float4 a = ((const float4*)g_scale)[c4];
    float4 c = ((const float4*)g_shift)[c4];
    float4 r;
    r.x = fmaxf(0.f, a.x * h.x + c.x);
    r.y = fmaxf(0.f, a.y * h.y + c.y);
    r.z = fmaxf(0.f, a.z * h.z + c.z);
    r.w = fmaxf(0.f, a.w * h.w + c.w);
    ((float4*)g_Hn)[idx] = r;
}

// ---------------- launcher ----------------
extern "C" void kernel_launch(void* const* d_in, const int* in_sizes, int n_in,
                              void* d_out, int out_size) {
    const float* x   = (const float*)d_in[0];
    const int*   ei  = (const int*)d_in[1];
    const float* W1  = (const float*)d_in[2];
    const float* b1  = (const float*)d_in[3];
    const float* g1  = (const float*)d_in[4];
    const float* bt1 = (const float*)d_in[5];
    const float* W2  = (const float*)d_in[6];
    const float* b2  = (const float*)d_in[7];
    const float* g2  = (const float*)d_in[8];
    const float* bt2 = (const float*)d_in[9];
    const float* W3  = (const float*)d_in[10];
    const float* b3  = (const float*)d_in[11];
    float* out = (float*)d_out;

    const int E = in_sizes[1] / 2;   // 1600000
    const int M = in_sizes[0] / DIN; // 100000

    const int TB = 256;
    dim3 nodeGrid((NNODES + TB - 1) / TB);
    dim3 edgeGrid((E + TB - 1) / TB);
    dim3 gemmGrid((M + 127) / 128);
    dim3 aggGrid((NNODES + 7) / 8);     // 8 warps / block
    dim3 applyGrid((NNODES * (DH / 4) + TB - 1) / TB);

    // --- graph normalization + CSR build ---
    k_zero_node_ints<<<nodeGrid, TB>>>();
    k_count_deg<<<edgeGrid, TB>>>(ei, E);
    k_dinv<<<nodeGrid, TB>>>();
    k_scan<<<1, 1024>>>(NNODES, E);
    k_scatter<<<edgeGrid, TB>>>(ei, E);

    // --- layer 1: conv(x, W1, b1) -> BN -> ReLU ---
    k_gemm<DH, 8, 16, true><<<gemmGrid, 256>>>(x, W1, M, DIN);
    k_agg<DH, false><<<aggGrid, 256>>>(b1, nullptr);
    k_zero_stats<<<1, 256>>>();
    k_stats<<<1024, 256>>>();
    k_bnfinal<<<1, DH>>>(g1, bt1);
    k_apply_relu<<<applyGrid, TB>>>();

    // --- layer 2: conv(h, W2, b2) -> BN -> ReLU ---
    k_gemm<DH, 8, 16, false><<<gemmGrid, 256>>>(nullptr, W2, M, DH);
    k_agg<DH, false><<<aggGrid, 256>>>(b2, nullptr);
    k_zero_stats<<<1, 256>>>();
    k_stats<<<1024, 256>>>();
    k_bnfinal<<<1, DH>>>(g2, bt2);
    k_apply_relu<<<applyGrid, TB>>>();

    // --- layer 3: conv(h, W3, b3) -> d_out ---
    k_gemm<DOUT, 4, 16, false><<<gemmGrid, 256>>>(nullptr, W3, M, DH);
    k_agg<DOUT, true><<<aggGrid, 256>>>(b3, out);
}

// round 4
// speedup vs baseline: 1.3681x; 1.3681x over previous
#include <cuda_runtime.h>
#include <mma.h>

using namespace nvcuda;

#define NNODES 100000
#define NEDGES 1600000
#define DIN 256
#define DH 128
#define DOUT 64
#define BN_EPS 1e-5f
#define NB_SCAN 391   // ceil(100000/256)

// ---------------- static device scratch ----------------
__device__ float g_dinv[NNODES];
__device__ int   g_deg[NNODES];
__device__ int   g_cursor[NNODES];
__device__ int   g_rowptr[NNODES + 1];
__device__ int   g_bsum[512];
__device__ int   g_col[NEDGES];
__device__ float g_wgt[NEDGES];
__device__ float g_H [NNODES * DH];   // GEMM output (XW)
__device__ float g_A [NNODES * DH];   // aggregated conv output (pre-BN)
__device__ float g_stats[2 * DH];     // column sums / sumsq
__device__ float g_scale[DH];
__device__ float g_shift[DH];

// ---------------- setup kernels ----------------
__global__ void k_zero_node_ints() {
    int i = blockIdx.x * blockDim.x + threadIdx.x;
    if (i < NNODES) { g_deg[i] = 0; g_cursor[i] = 0; }
}

__global__ void k_count_deg(const int* __restrict__ ei, int E) {
    int e = blockIdx.x * blockDim.x + threadIdx.x;
    if (e < E) atomicAdd(&g_deg[ei[E + e]], 1);
}

__global__ void k_dinv() {
    int i = blockIdx.x * blockDim.x + threadIdx.x;
    if (i < NNODES) g_dinv[i] = rsqrtf((float)(g_deg[i] + 1));
}

// ---- multi-block exclusive scan: deg -> rowptr ----
__global__ void k_scan1() {               // per-block reduce
    __shared__ int s[256];
    int t = threadIdx.x;
    int i = blockIdx.x * 256 + t;
    int v = (i < NNODES) ? g_deg[i] : 0;
    s[t] = v;
    __syncthreads();
#pragma unroll
    for (int off = 128; off > 0; off >>= 1) {
        if (t < off) s[t] += s[t + off];
        __syncthreads();
    }
    if (t == 0) g_bsum[blockIdx.x] = s[0];
}

__global__ void k_scan2() {               // scan of block sums (1 block, 512 thr)
    __shared__ int s[512];
    int t = threadIdx.x;
    int v = (t < NB_SCAN) ? g_bsum[t] : 0;
    s[t] = v;
    __syncthreads();
    for (int off = 1; off < 512; off <<= 1) {
        int a = (t >= off) ? s[t - off] : 0;
        __syncthreads();
        s[t] += a;
        __syncthreads();
    }
    g_bsum[t] = s[t] - v;                 // exclusive
}

__global__ void k_scan3(int E) {          // block-local scan + offset
    __shared__ int s[256];
    int t = threadIdx.x;
    int i = blockIdx.x * 256 + t;
    int v = (i < NNODES) ? g_deg[i] : 0;
    s[t] = v;
    __syncthreads();
    for (int off = 1; off < 256; off <<= 1) {
        int a = (t >= off) ? s[t - off] : 0;
        __syncthreads();
        s[t] += a;
        __syncthreads();
    }
    if (i < NNODES) g_rowptr[i] = g_bsum[blockIdx.x] + s[t] - v;
    if (i == 0) g_rowptr[NNODES] = E;
}

__global__ void k_scatter(const int* __restrict__ ei, int E) {
    int e = blockIdx.x * blockDim.x + threadIdx.x;
    if (e >= E) return;
    int s = ei[e];
    int d = ei[E + e];
    int pos = g_rowptr[d] + atomicAdd(&g_cursor[d], 1);
    g_col[pos] = s;
    g_wgt[pos] = g_dinv[s] * g_dinv[d];
}

// ---------------- WMMA TF32 GEMM ----------------
// C(g_H)[M x BN] = op(A)[M x K] @ B[K x BN]
// FUSE=false: A = Aext (external input x)
// FUSE=true:  A = relu(g_A * scale[k] + shift[k])   (device buffer, BN fusion)
// BM=128, BK=32; 8 warps in 4x2; warp tile 32 x (BN/2); wmma m16n16k8 tf32.
template <int BN, bool FUSE>
__global__ void __launch_bounds__(256)
k_gemm_wmma(const float* __restrict__ Aext, const float* __restrict__ B, int M, int K) {
    constexpr int BM = 128, BK = 32;
    constexpr int SAP = 40;              // padded lds (floats), mult of 8
    constexpr int SBP = BN + 8;
    constexpr int WROWS = 4, WCOLS = 2;
    constexpr int WM = BM / WROWS;       // 32
    constexpr int WN = BN / WCOLS;       // 64 or 32
    constexpr int MT = WM / 16;          // 2
    constexpr int NT = WN / 16;          // 4 or 2

    __shared__ __align__(16) float sA[BM * SAP];
    __shared__ __align__(16) float sB[BK * SBP];

    // CRITICAL: device-symbol buffer must be referenced from device code only.
    const float* A = FUSE ? (const float*)g_A : Aext;

    const int tid = threadIdx.x;
    const int wid = tid >> 5;
    const int wm = wid / WCOLS;
    const int wn = wid % WCOLS;
    const int row0 = blockIdx.x * BM;

    wmma::fragment<wmma::accumulator, 16, 16, 8, float> acc[MT][NT];
#pragma unroll
    for (int i = 0; i < MT; i++)
#pragma unroll
        for (int j = 0; j < NT; j++) wmma::fill_fragment(acc[i][j], 0.0f);

    constexpr int NPB = (BK * BN / 4) / 256;   // B float4 passes

    for (int kt = 0; kt < K; kt += BK) {
        // --- load A tile (optionally fused BN+ReLU), convert to tf32 ---
#pragma unroll
        for (int p = 0; p < 4; p++) {
            int idx = tid + p * 256;          // 1024 float4s = 128 x 32
            int r = idx >> 3;                 // 8 float4 per row
            int c4 = idx & 7;
            int gr = row0 + r;
            float4 v = make_float4(0.f, 0.f, 0.f, 0.f);
            if (gr < M) v = *(const float4*)(A + (size_t)gr * K + kt + c4 * 4);
            if (FUSE) {
                float4 sc = *(const float4*)(g_scale + kt + c4 * 4);
                float4 sh = *(const float4*)(g_shift + kt + c4 * 4);
                v.x = fmaxf(0.f, v.x * sc.x + sh.x);
                v.y = fmaxf(0.f, v.y * sc.y + sh.y);
                v.z = fmaxf(0.f, v.z * sc.z + sh.z);
                v.w = fmaxf(0.f, v.w * sc.w + sh.w);
            }
            float* d = &sA[r * SAP + c4 * 4];
            d[0] = wmma::__float_to_tf32(v.x);
            d[1] = wmma::__float_to_tf32(v.y);
            d[2] = wmma::__float_to_tf32(v.z);
            d[3] = wmma::__float_to_tf32(v.w);
        }
        // --- load B tile, convert to tf32 ---
#pragma unroll
        for (int p = 0; p < NPB; p++) {
            int idx = tid + p * 256;
            int r = idx / (BN / 4);
            int c4 = idx % (BN / 4);
            float4 v = *(const float4*)(B + (size_t)(kt + r) * BN + c4 * 4);
            float* d = &sB[r * SBP + c4 * 4];
            d[0] = wmma::__float_to_tf32(v.x);
            d[1] = wmma::__float_to_tf32(v.y);
            d[2] = wmma::__float_to_tf32(v.z);
            d[3] = wmma::__float_to_tf32(v.w);
        }
        __syncthreads();

#pragma unroll
        for (int kk = 0; kk < BK; kk += 8) {
            wmma::fragment<wmma::matrix_a, 16, 16, 8, wmma::precision::tf32,
                           wmma::row_major> af[MT];
            wmma::fragment<wmma::matrix_b, 16, 16, 8, wmma::precision::tf32,
                           wmma::row_major> bf[NT];
#pragma unroll
            for (int mt = 0; mt < MT; mt++)
                wmma::load_matrix_sync(af[mt],
                    &sA[(wm * WM + mt * 16) * SAP + kk], SAP);
#pragma unroll
            for (int nt = 0; nt < NT; nt++)
                wmma::load_matrix_sync(bf[nt],
                    &sB[kk * SBP + wn * WN + nt * 16], SBP);
#pragma unroll
            for (int mt = 0; mt < MT; mt++)
#pragma unroll
                for (int nt = 0; nt < NT; nt++)
                    wmma::mma_sync(acc[mt][nt], af[mt], bf[nt], acc[mt][nt]);
        }
        __syncthreads();
    }

    // --- epilogue (M % 16 == 0, so 16-row fragments are all-or-nothing) ---
    float* C = g_H;
#pragma unroll
    for (int mt = 0; mt < MT; mt++) {
        int gr = row0 + wm * WM + mt * 16;
        if (gr >= M) continue;
#pragma unroll
        for (int nt = 0; nt < NT; nt++)
            wmma::store_matrix_sync(C + (size_t)gr * BN + wn * WN + nt * 16,
                                    acc[mt][nt], BN, wmma::mem_row_major);
    }
}

// ---------------- aggregation: warp per dst node, CSR gather-sum ----------------
template <int D, bool EXT_OUT>
__global__ void k_agg(const float* __restrict__ bias, float* __restrict__ out_ext) {
    constexpr int VEC = D / 32;
    int w = blockIdx.x * (blockDim.x >> 5) + (threadIdx.x >> 5);
    if (w >= NNODES) return;
    int lane = threadIdx.x & 31;
    int base = lane * VEC;
    const float* H = g_H;
    float* out = EXT_OUT ? out_ext : (float*)g_A;

    float acc[VEC], acc2[VEC];
    float di = g_dinv[w];
    float self = di * di;

    if constexpr (VEC == 4) {
        float4 h = *(const float4*)(H + (size_t)w * D + base);
        acc[0] = bias[base + 0] + self * h.x;
        acc[1] = bias[base + 1] + self * h.y;
        acc[2] = bias[base + 2] + self * h.z;
        acc[3] = bias[base + 3] + self * h.w;
        acc2[0] = acc2[1] = acc2[2] = acc2[3] = 0.f;
    } else {
        float2 h = *(const float2*)(H + (size_t)w * D + base);
        acc[0] = bias[base + 0] + self * h.x;
        acc[1] = bias[base + 1] + self * h.y;
        acc2[0] = acc2[1] = 0.f;
    }

    int j = g_rowptr[w];
    int je = g_rowptr[w + 1];
    for (; j + 1 < je; j += 2) {
        int   s0 = __ldg(&g_col[j]),     s1 = __ldg(&g_col[j + 1]);
        float w0 = __ldg(&g_wgt[j]),     w1 = __ldg(&g_wgt[j + 1]);
        const float* h0 = H + (size_t)s0 * D + base;
        const float* h1 = H + (size_t)s1 * D + base;
        if constexpr (VEC == 4) {
            float4 a = *(const float4*)h0;
            float4 b = *(const float4*)h1;
            acc[0]  += w0 * a.x; acc[1]  += w0 * a.y;
            acc[2]  += w0 * a.z; acc[3]  += w0 * a.w;
            acc2[0] += w1 * b.x; acc2[1] += w1 * b.y;
            acc2[2] += w1 * b.z; acc2[3] += w1 * b.w;
        } else {
            float2 a = *(const float2*)h0;
            float2 b = *(const float2*)h1;
            acc[0]  += w0 * a.x; acc[1]  += w0 * a.y;
            acc2[0] += w1 * b.x; acc2[1] += w1 * b.y;
        }
    }
    if (j < je) {
        int   s0 = __ldg(&g_col[j]);
        float w0 = __ldg(&g_wgt[j]);
        const float* h0 = H + (size_t)s0 * D + base;
        if constexpr (VEC == 4) {
            float4 a = *(const float4*)h0;
            acc[0] += w0 * a.x; acc[1] += w0 * a.y;
            acc[2] += w0 * a.z; acc[3] += w0 * a.w;
        } else {
            float2 a = *(const float2*)h0;
            acc[0] += w0 * a.x; acc[1] += w0 * a.y;
        }
    }

    if constexpr (VEC == 4) {
        *(float4*)(out + (size_t)w * D + base) =
            make_float4(acc[0] + acc2[0], acc[1] + acc2[1],
                        acc[2] + acc2[2], acc[3] + acc2[3]);
    } else {
        *(float2*)(out + (size_t)w * D + base) =
            make_float2(acc[0] + acc2[0], acc[1] + acc2[1]);
    }
}

// ---------------- BatchNorm stats ----------------
__global__ void k_zero_stats() {
    int t = threadIdx.x;
    if (t < 2 * DH) g_stats[t] = 0.f;
}

__global__ void k_stats() {
    int col = threadIdx.x & (DH - 1);
    int rsub = threadIdx.x >> 7;
    float s = 0.f, sq = 0.f;
    for (int row = blockIdx.x * 2 + rsub; row < NNODES; row += gridDim.x * 2) {
        float v = g_A[(size_t)row * DH + col];
        s += v; sq += v * v;
    }
    atomicAdd(&g_stats[col], s);
    atomicAdd(&g_stats[DH + col], sq);
}

__global__ void k_bnfinal(const float* __restrict__ g, const float* __restrict__ bt) {
    int t = threadIdx.x;
    if (t >= DH) return;
    float invN = 1.0f / (float)NNODES;
    float mu = g_stats[t] * invN;
    float var = g_stats[DH + t] * invN - mu * mu;
    float r = rsqrtf(var + BN_EPS);
    float a = g[t] * r;
    g_scale[t] = a;
    g_shift[t] = bt[t] - mu * a;
}

// ---------------- launcher ----------------
extern "C" void kernel_launch(void* const* d_in, const int* in_sizes, int n_in,
                              void* d_out, int out_size) {
    const float* x   = (const float*)d_in[0];
    const int*   ei  = (const int*)d_in[1];
    const float* W1  = (const float*)d_in[2];
    const float* b1  = (const float*)d_in[3];
    const float* g1  = (const float*)d_in[4];
    const float* bt1 = (const float*)d_in[5];
    const float* W2  = (const float*)d_in[6];
    const float* b2  = (const float*)d_in[7];
    const float* g2  = (const float*)d_in[8];
    const float* bt2 = (const float*)d_in[9];
    const float* W3  = (const float*)d_in[10];
    const float* b3  = (const float*)d_in[11];
    float* out = (float*)d_out;

    const int E = in_sizes[1] / 2;
    const int M = in_sizes[0] / DIN;

    const int TB = 256;
    dim3 nodeGrid((NNODES + TB - 1) / TB);
    dim3 edgeGrid((E + TB - 1) / TB);
    dim3 gemmGrid((M + 127) / 128);
    dim3 aggGrid((NNODES + 7) / 8);

    // --- graph normalization + CSR build ---
    k_zero_node_ints<<<nodeGrid, TB>>>();
    k_count_deg<<<edgeGrid, TB>>>(ei, E);
    k_dinv<<<nodeGrid, TB>>>();
    k_scan1<<<NB_SCAN, 256>>>();
    k_scan2<<<1, 512>>>();
    k_scan3<<<NB_SCAN, 256>>>(E);
    k_scatter<<<edgeGrid, TB>>>(ei, E);

    // --- layer 1 (A = external x) ---
    k_gemm_wmma<DH, false><<<gemmGrid, 256>>>(x, W1, M, DIN);
    k_agg<DH, false><<<aggGrid, 256>>>(b1, nullptr);
    k_zero_stats<<<1, 256>>>();
    k_stats<<<2048, 256>>>();
    k_bnfinal<<<1, DH>>>(g1, bt1);

    // --- layer 2 (A = g_A read in device code; BN1+ReLU fused into A-load) ---
    k_gemm_wmma<DH, true><<<gemmGrid, 256>>>(nullptr, W2, M, DH);
    k_agg<DH, false><<<aggGrid, 256>>>(b2, nullptr);
    k_zero_stats<<<1, 256>>>();
    k_stats<<<2048, 256>>>();
    k_bnfinal<<<1, DH>>>(g2, bt2);

    // --- layer 3 (A = g_A; BN2+ReLU fused into A-load) ---
    k_gemm_wmma<DOUT, true><<<gemmGrid, 256>>>(nullptr, W3, M, DH);
    k_agg<DOUT, true><<<aggGrid, 256>>>(b3, out);
}